// round 1
// baseline (speedup 1.0000x reference)
#include <cuda_runtime.h>
#include <cuda_bf16.h>

// ---------------------------------------------------------------------------
// GRU stack: 4 layers (256 -> 256), B=128, T=384, reset_after=True (Keras).
// Phase A (per layer): xp = X @ W + b_in   (big parallel GEMM, fp32)
// Phase B (per layer): persistent scan kernel, weights in SMEM, group barriers.
// ---------------------------------------------------------------------------

#define BATCH   128
#define T_STEPS 384
#define UNITS   256
#define FEAT    256
#define G3      768            // 3 * UNITS
#define MROWS   (BATCH * T_STEPS)   // 49152

// scratch (device globals: sanctioned scratch mechanism)
__device__ float    g_xp[MROWS * G3];      // [B*T, 768] input projections
__device__ float    g_hseq[MROWS * UNITS]; // [B*T, 256] hidden sequence
__device__ unsigned g_bar[16 * 32];        // 16 group barrier counters, 128B apart

// ---------------------------------------------------------------------------
// barrier init (per-launch reset; counters are monotonic within a launch)
// ---------------------------------------------------------------------------
__global__ void init_bar_kernel() {
    if (threadIdx.x < 16) g_bar[threadIdx.x * 32] = 0u;
}

// ---------------------------------------------------------------------------
// SGEMM: C[M=49152, N=768] = A[M,256] @ W[256,768] + bias_in[768]
// 128x128x8 tiles, 256 threads, 8x8 per-thread register tile.
// ---------------------------------------------------------------------------
__global__ __launch_bounds__(256) void gemm_kernel(
    const float* __restrict__ X,     // external input (layer 0) or unused
    const float* __restrict__ W,     // [256, 768]
    const float* __restrict__ bin,   // [768] input bias
    int use_x)
{
    const int K = 256, N = G3;
    const float* A = use_x ? X : g_hseq;

    __shared__ float As[8][128];
    __shared__ float Bs[8][128];

    int tid = threadIdx.x;
    int tx = tid & 15;        // 0..15 (col group)
    int ty = tid >> 4;        // 0..15 (row group)
    int bm = blockIdx.y * 128;
    int bn = blockIdx.x * 128;

    float acc[8][8];
#pragma unroll
    for (int i = 0; i < 8; i++)
#pragma unroll
        for (int j = 0; j < 8; j++) acc[i][j] = 0.f;

    int arow = tid >> 1;            // 0..127
    int acol = (tid & 1) * 4;       // 0 or 4
    int brow = tid >> 5;            // 0..7
    int bcol = (tid & 31) * 4;      // 0..124

    const float* Ap = A + (bm + arow) * K + acol;
    const float* Wp = W + brow * N + bn + bcol;

    for (int k0 = 0; k0 < K; k0 += 8) {
        float4 a4 = *(const float4*)(Ap + k0);
        float4 b4 = *(const float4*)(Wp + k0 * N);
        __syncthreads();
        As[acol + 0][arow] = a4.x;
        As[acol + 1][arow] = a4.y;
        As[acol + 2][arow] = a4.z;
        As[acol + 3][arow] = a4.w;
        *(float4*)&Bs[brow][bcol] = b4;
        __syncthreads();
#pragma unroll
        for (int kk = 0; kk < 8; kk++) {
            float ra[8], rb[8];
            *(float4*)(ra)     = *(const float4*)&As[kk][ty * 4];
            *(float4*)(ra + 4) = *(const float4*)&As[kk][64 + ty * 4];
            *(float4*)(rb)     = *(const float4*)&Bs[kk][tx * 4];
            *(float4*)(rb + 4) = *(const float4*)&Bs[kk][64 + tx * 4];
#pragma unroll
            for (int i = 0; i < 8; i++)
#pragma unroll
                for (int j = 0; j < 8; j++)
                    acc[i][j] += ra[i] * rb[j];
        }
    }

    // epilogue: add input bias, write xp
#pragma unroll
    for (int i = 0; i < 8; i++) {
        int row = (i < 4) ? (ty * 4 + i) : (64 + ty * 4 + (i - 4));
#pragma unroll
        for (int jh = 0; jh < 2; jh++) {
            int col = jh * 64 + tx * 4;
            float4 v;
            v.x = acc[i][jh * 4 + 0] + bin[bn + col + 0];
            v.y = acc[i][jh * 4 + 1] + bin[bn + col + 1];
            v.z = acc[i][jh * 4 + 2] + bin[bn + col + 2];
            v.w = acc[i][jh * 4 + 3] + bin[bn + col + 3];
            *(float4*)&g_xp[(bm + row) * N + bn + col] = v;
        }
    }
}

// ---------------------------------------------------------------------------
// Recurrent scan. Grid (8 unit-tiles, 16 batch-tiles) = 128 blocks, all
// co-resident (<=148 SMs). Block owns 8 batch rows x 32 units; its 96 KB
// weight slice lives in SMEM for all 384 steps. Sync: per-batch-tile group
// barrier (8 blocks) via monotonic L2 atomic counter. h exchanged via L2
// (ld.cg / st.cg to avoid L1 staleness).
// Threads: 256 = {ks:2} x {b:8} x {unit-pair:16}; k split in half, reduced
// through SMEM.
// ---------------------------------------------------------------------------
#define SCAN_SMEM ((3 * 256 * 32 + 8 * 260 + 128 * 6) * 4)

__device__ __forceinline__ float sigmoidf_(float x) {
    return 1.f / (1.f + __expf(-x));
}
__device__ __forceinline__ float tanhf_(float x) {
    float s = 1.f / (1.f + __expf(-2.f * x));
    return 2.f * s - 1.f;
}

__global__ __launch_bounds__(256) void scan_kernel(
    const float* __restrict__ RK,    // recurrent kernel [256, 768]
    const float* __restrict__ brec,  // recurrent bias [768]
    int base)                        // barrier base = 3072 * layer_index
{
    extern __shared__ float smem[];
    float* sR   = smem;                      // [3][256][32] = 24576 floats
    float* sh   = smem + 24576;              // [8][260]     (padded h tile)
    float* sred = smem + 24576 + 8 * 260;    // [128][6]

    int ut = blockIdx.x;        // 0..7  unit tile
    int bt = blockIdx.y;        // 0..15 batch tile
    int u0 = ut * 32;
    int b0 = bt * 8;
    int tid = threadIdx.x;

    // load weight slice: sR[g][k][uu] = RK[k*768 + g*256 + u0+uu]
    for (int idx = tid; idx < 24576; idx += 256) {
        int uu = idx & 31;
        int k  = (idx >> 5) & 255;
        int g  = idx >> 13;
        sR[idx] = RK[k * G3 + g * 256 + u0 + uu];
    }
    // zero h tile (h0 = 0)
    for (int i = tid; i < 8 * 260; i += 256) sh[i] = 0.f;

    int ks = tid >> 7;          // k-split half
    int rr = tid & 127;
    int b  = rr >> 4;           // 0..7 local batch row
    int up = rr & 15;           // unit pair index
    int u  = up * 2;            // local unit (even)

    float2 bz  = *(const float2*)(brec + 0   + u0 + u);
    float2 brr = *(const float2*)(brec + 256 + u0 + u);
    float2 bh  = *(const float2*)(brec + 512 + u0 + u);

    unsigned* bar = &g_bar[bt * 32];

    __syncthreads();

    for (int t = 0; t < T_STEPS; t++) {
        // prefetch xp(t) early (independent of barrier)
        float2 mz, mr, mh;
        if (ks == 0) {
            const float* xrow = g_xp + ((b0 + b) * T_STEPS + t) * G3;
            mz = *(const float2*)(xrow + 0   + u0 + u);
            mr = *(const float2*)(xrow + 256 + u0 + u);
            mh = *(const float2*)(xrow + 512 + u0 + u);
        }

        if (t > 0) {
            // wait: all 8 blocks of this batch tile finished step t-1
            if (tid == 0) {
                unsigned target = (unsigned)base + 8u * (unsigned)t;
                while (atomicAdd(bar, 0u) < target) { }
                __threadfence();
            }
            __syncthreads();
            // load h(t-1) for our 8 batch rows (all 256 units) via L2
            for (int p = tid; p < 512; p += 256) {
                int r_i = p >> 6;
                int off = (p & 63) * 4;
                float4 v = __ldcg((const float4*)(g_hseq +
                            ((b0 + r_i) * T_STEPS + (t - 1)) * UNITS + off));
                *(float4*)&sh[r_i * 260 + off] = v;
            }
            __syncthreads();
        }

        // partial GEMM over our k half
        float2 az = {0.f, 0.f}, ar = {0.f, 0.f}, ah = {0.f, 0.f};
        const float* shb = sh + b * 260;
        int kbeg = ks * 128;
#pragma unroll 8
        for (int k = kbeg; k < kbeg + 128; k++) {
            float  hk = shb[k];
            float2 wz = *(const float2*)(sR +          k * 32 + u);
            float2 wr = *(const float2*)(sR +  8192 +  k * 32 + u);
            float2 wh = *(const float2*)(sR + 16384 +  k * 32 + u);
            az.x += hk * wz.x;  az.y += hk * wz.y;
            ar.x += hk * wr.x;  ar.y += hk * wr.y;
            ah.x += hk * wh.x;  ah.y += hk * wh.y;
        }

        if (ks == 1) {
            float* d = sred + rr * 6;
            d[0] = az.x; d[1] = az.y; d[2] = ar.x;
            d[3] = ar.y; d[4] = ah.x; d[5] = ah.y;
        }
        __syncthreads();

        if (ks == 0) {
            const float* d = sred + rr * 6;
            az.x += d[0]; az.y += d[1];
            ar.x += d[2]; ar.y += d[3];
            ah.x += d[4]; ah.y += d[5];

            float hp0 = shb[u0 + u];
            float hp1 = shb[u0 + u + 1];

            float z0 = sigmoidf_(mz.x + az.x + bz.x);
            float r0 = sigmoidf_(mr.x + ar.x + brr.x);
            float c0 = tanhf_(mh.x + r0 * (ah.x + bh.x));
            float hn0 = z0 * hp0 + (1.f - z0) * c0;

            float z1 = sigmoidf_(mz.y + az.y + bz.y);
            float r1 = sigmoidf_(mr.y + ar.y + brr.y);
            float c1 = tanhf_(mh.y + r1 * (ah.y + bh.y));
            float hn1 = z1 * hp1 + (1.f - z1) * c1;

            float2 hv = make_float2(hn0, hn1);
            __stcg((float2*)(g_hseq + ((b0 + b) * T_STEPS + t) * UNITS + u0 + u), hv);
        }

        // publish h(t): fence + arrive
        __threadfence();
        __syncthreads();
        if (tid == 0) atomicAdd(bar, 1u);
    }
}

// ---------------------------------------------------------------------------
// final output: d_out[b, u] = hseq[b, T-1, u]
// ---------------------------------------------------------------------------
__global__ void copy_out_kernel(float* __restrict__ out) {
    int i = blockIdx.x * 256 + threadIdx.x;   // 0..32767
    int b = i >> 8;
    int u = i & 255;
    out[i] = g_hseq[(b * T_STEPS + (T_STEPS - 1)) * UNITS + u];
}

// ---------------------------------------------------------------------------
extern "C" void kernel_launch(void* const* d_in, const int* in_sizes, int n_in,
                              void* d_out, int out_size) {
    (void)in_sizes; (void)n_in; (void)out_size;
    const float* x     = (const float*)d_in[0];  // [128,384,256]
    const float* k0    = (const float*)d_in[1];  // [256,768]
    const float* rk0   = (const float*)d_in[2];  // [256,768]
    const float* b0    = (const float*)d_in[3];  // [2,768]
    const float* kern  = (const float*)d_in[4];  // [3,256,768]
    const float* rkern = (const float*)d_in[5];  // [3,256,768]
    const float* bias  = (const float*)d_in[6];  // [3,2,768]
    float* out = (float*)d_out;                  // [128,256]

    cudaFuncSetAttribute(scan_kernel,
        cudaFuncAttributeMaxDynamicSharedMemorySize, SCAN_SMEM);

    init_bar_kernel<<<1, 32>>>();

    dim3 ggrid(G3 / 128, MROWS / 128);   // (6, 384)
    dim3 sgrid(8, 16);                   // 128 blocks, all co-resident

    // layer 0
    gemm_kernel<<<ggrid, 256>>>(x, k0, b0, 1);
    scan_kernel<<<sgrid, 256, SCAN_SMEM>>>(rk0, b0 + G3, 0);

    // layers 1..3
    for (int l = 0; l < 3; l++) {
        gemm_kernel<<<ggrid, 256>>>(nullptr, kern + l * 256 * G3,
                                    bias + l * 2 * G3, 0);
        scan_kernel<<<sgrid, 256, SCAN_SMEM>>>(rkern + l * 256 * G3,
                                    bias + l * 2 * G3 + G3,
                                    (l + 1) * 8 * T_STEPS);
    }

    copy_out_kernel<<<BATCH, 256>>>(out);
}

// round 2
// speedup vs baseline: 1.1117x; 1.1117x over previous
#include <cuda_runtime.h>
#include <cuda_bf16.h>

// ---------------------------------------------------------------------------
// GRU stack: 4 layers (256 -> 256), B=128, T=384, reset_after=True (Keras).
// Phase A (per layer): xp = X @ W + b_in   (fp32 GEMM, double-buffered)
// Phase B (per layer): persistent scan, weights in SMEM, release/acquire flags.
// ---------------------------------------------------------------------------

#define BATCH   128
#define T_STEPS 384
#define UNITS   256
#define FEAT    256
#define G3      768
#define MROWS   (BATCH * T_STEPS)   // 49152

__device__ float    g_xp[MROWS * G3];      // [B*T, 768] input projections
__device__ float    g_hseq[MROWS * UNITS]; // [B*T, 256] hidden sequence
__device__ unsigned g_flag[16 * 32];       // flags[bt*32 + ut], monotonic steps

// ---------------------------------------------------------------------------
__global__ void init_flags_kernel() {
    g_flag[threadIdx.x] = 0u;   // 512 threads
}

// ---------------------------------------------------------------------------
__device__ __forceinline__ unsigned ld_acquire_gpu(const unsigned* p) {
    unsigned v;
    asm volatile("ld.acquire.gpu.global.u32 %0, [%1];" : "=r"(v) : "l"(p) : "memory");
    return v;
}
__device__ __forceinline__ void st_release_gpu(unsigned* p, unsigned v) {
    asm volatile("st.release.gpu.global.u32 [%0], %1;" :: "l"(p), "r"(v) : "memory");
}

// ---------------------------------------------------------------------------
// SGEMM: C[M=49152, N=768] = A[M,256] @ W[256,768] + bias_in[768]
// 128x128x8 tiles, 256 threads, 8x8 register tile, 2-stage smem double buffer.
// ---------------------------------------------------------------------------
__global__ __launch_bounds__(256, 2) void gemm_kernel(
    const float* __restrict__ X,
    const float* __restrict__ W,
    const float* __restrict__ bin,
    int use_x)
{
    const int K = 256, N = G3;
    const float* A = use_x ? X : g_hseq;

    __shared__ float As[2][8][128];
    __shared__ float Bs[2][8][128];

    int tid = threadIdx.x;
    int tx = tid & 15;
    int ty = tid >> 4;
    int bm = blockIdx.y * 128;
    int bn = blockIdx.x * 128;

    float acc[8][8];
#pragma unroll
    for (int i = 0; i < 8; i++)
#pragma unroll
        for (int j = 0; j < 8; j++) acc[i][j] = 0.f;

    int arow = tid >> 1;
    int acol = (tid & 1) * 4;
    int brow = tid >> 5;
    int bcol = (tid & 31) * 4;

    const float* Ap = A + (bm + arow) * K + acol;
    const float* Wp = W + brow * N + bn + bcol;

    // preload tile 0
    {
        float4 a4 = *(const float4*)(Ap);
        float4 b4 = *(const float4*)(Wp);
        As[0][acol + 0][arow] = a4.x;
        As[0][acol + 1][arow] = a4.y;
        As[0][acol + 2][arow] = a4.z;
        As[0][acol + 3][arow] = a4.w;
        *(float4*)&Bs[0][brow][bcol] = b4;
    }
    __syncthreads();

    int buf = 0;
    for (int k0 = 8; k0 <= K; k0 += 8) {
        float4 a4n, b4n;
        if (k0 < K) {
            a4n = *(const float4*)(Ap + k0);
            b4n = *(const float4*)(Wp + k0 * N);
        }
#pragma unroll
        for (int kk = 0; kk < 8; kk++) {
            float ra[8], rb[8];
            *(float4*)(ra)     = *(const float4*)&As[buf][kk][ty * 4];
            *(float4*)(ra + 4) = *(const float4*)&As[buf][kk][64 + ty * 4];
            *(float4*)(rb)     = *(const float4*)&Bs[buf][kk][tx * 4];
            *(float4*)(rb + 4) = *(const float4*)&Bs[buf][kk][64 + tx * 4];
#pragma unroll
            for (int i = 0; i < 8; i++)
#pragma unroll
                for (int j = 0; j < 8; j++)
                    acc[i][j] += ra[i] * rb[j];
        }
        if (k0 < K) {
            int nb = buf ^ 1;
            As[nb][acol + 0][arow] = a4n.x;
            As[nb][acol + 1][arow] = a4n.y;
            As[nb][acol + 2][arow] = a4n.z;
            As[nb][acol + 3][arow] = a4n.w;
            *(float4*)&Bs[nb][brow][bcol] = b4n;
            __syncthreads();
            buf = nb;
        }
    }

#pragma unroll
    for (int i = 0; i < 8; i++) {
        int row = (i < 4) ? (ty * 4 + i) : (64 + ty * 4 + (i - 4));
#pragma unroll
        for (int jh = 0; jh < 2; jh++) {
            int col = jh * 64 + tx * 4;
            float4 v;
            v.x = acc[i][jh * 4 + 0] + bin[bn + col + 0];
            v.y = acc[i][jh * 4 + 1] + bin[bn + col + 1];
            v.z = acc[i][jh * 4 + 2] + bin[bn + col + 2];
            v.w = acc[i][jh * 4 + 3] + bin[bn + col + 3];
            *(float4*)&g_xp[(bm + row) * N + bn + col] = v;
        }
    }
}

// ---------------------------------------------------------------------------
// Recurrent scan. Grid (8 unit-tiles, 16 batch-tiles) = 128 blocks (1 wave).
// Block owns 8 batch rows x 32 units; 96 KB weight slice in SMEM.
// Sync: monotonic per-block flags with release/acquire; h via L2 (ld/st.cg).
// Own h slice is kept in SMEM (only 7 peer slices reloaded each step).
// ---------------------------------------------------------------------------
#define SCAN_SMEM ((3 * 256 * 32 + 8 * 260 + 128 * 6) * 4)

__device__ __forceinline__ float sigmoidf_(float x) {
    return 1.f / (1.f + __expf(-x));
}
__device__ __forceinline__ float tanhf_(float x) {
    float s = 1.f / (1.f + __expf(-2.f * x));
    return 2.f * s - 1.f;
}

__global__ __launch_bounds__(256) void scan_kernel(
    const float* __restrict__ RK,    // [256, 768]
    const float* __restrict__ brec,  // [768]
    int layer)
{
    extern __shared__ float smem[];
    float* sR   = smem;                      // [3][256][32]
    float* sh   = smem + 24576;              // [8][260]
    float* sred = smem + 24576 + 8 * 260;    // [128][6]

    int ut = blockIdx.x;
    int bt = blockIdx.y;
    int u0 = ut * 32;
    int b0 = bt * 8;
    int tid = threadIdx.x;

    for (int idx = tid; idx < 24576; idx += 256) {
        int uu = idx & 31;
        int k  = (idx >> 5) & 255;
        int g  = idx >> 13;
        sR[idx] = RK[k * G3 + g * 256 + u0 + uu];
    }
    for (int i = tid; i < 8 * 260; i += 256) sh[i] = 0.f;

    int ks = tid >> 7;
    int rr = tid & 127;
    int b  = rr >> 4;
    int up = rr & 15;
    int u  = up * 2;

    float2 bz  = *(const float2*)(brec + 0   + u0 + u);
    float2 brr = *(const float2*)(brec + 256 + u0 + u);
    float2 bh  = *(const float2*)(brec + 512 + u0 + u);

    unsigned* flags = &g_flag[bt * 32];
    unsigned base = (unsigned)layer * (unsigned)T_STEPS;

    __syncthreads();

    for (int t = 0; t < T_STEPS; t++) {
        // prefetch xp(t) before waiting (independent of the flags)
        float2 mz, mr, mh;
        if (ks == 0) {
            const float* xrow = g_xp + ((b0 + b) * T_STEPS + t) * G3;
            mz = *(const float2*)(xrow + 0   + u0 + u);
            mr = *(const float2*)(xrow + 256 + u0 + u);
            mh = *(const float2*)(xrow + 512 + u0 + u);
        }

        if (t > 0) {
            // wait for all 8 producers of this batch tile (own flag trivially set)
            if (tid < 8) {
                unsigned target = base + (unsigned)t;
                while (ld_acquire_gpu(&flags[tid]) < target) { }
            }
            __syncthreads();
            // load the 7 peer h slices (own slice already in sh)
            for (int p = tid; p < 448; p += 256) {
                int s   = p >> 6;             // 0..6
                int r_i = (p >> 3) & 7;       // 0..7 local batch row
                int c   = p & 7;              // float4 index within 32 units
                int ut2 = s + (s >= ut);
                float4 v = __ldcg((const float4*)(g_hseq +
                            ((b0 + r_i) * T_STEPS + (t - 1)) * UNITS + ut2 * 32 + c * 4));
                *(float4*)&sh[r_i * 260 + ut2 * 32 + c * 4] = v;
            }
            __syncthreads();
        }

        // partial GEMM over this thread's k half
        float2 az = {0.f, 0.f}, ar = {0.f, 0.f}, ah = {0.f, 0.f};
        const float* shb = sh + b * 260;
        int kbeg = ks * 128;
#pragma unroll 8
        for (int k = kbeg; k < kbeg + 128; k++) {
            float  hk = shb[k];
            float2 wz = *(const float2*)(sR +          k * 32 + u);
            float2 wr = *(const float2*)(sR +  8192 +  k * 32 + u);
            float2 wh = *(const float2*)(sR + 16384 +  k * 32 + u);
            az.x += hk * wz.x;  az.y += hk * wz.y;
            ar.x += hk * wr.x;  ar.y += hk * wr.y;
            ah.x += hk * wh.x;  ah.y += hk * wh.y;
        }

        if (ks == 1) {
            float* d = sred + rr * 6;
            d[0] = az.x; d[1] = az.y; d[2] = ar.x;
            d[3] = ar.y; d[4] = ah.x; d[5] = ah.y;
        }
        __syncthreads();

        if (ks == 0) {
            const float* d = sred + rr * 6;
            az.x += d[0]; az.y += d[1];
            ar.x += d[2]; ar.y += d[3];
            ah.x += d[4]; ah.y += d[5];

            float hp0 = shb[u0 + u];
            float hp1 = shb[u0 + u + 1];

            float z0 = sigmoidf_(mz.x + az.x + bz.x);
            float r0 = sigmoidf_(mr.x + ar.x + brr.x);
            float c0 = tanhf_(mh.x + r0 * (ah.x + bh.x));
            float hn0 = z0 * hp0 + (1.f - z0) * c0;

            float z1 = sigmoidf_(mz.y + az.y + bz.y);
            float r1 = sigmoidf_(mr.y + ar.y + brr.y);
            float c1 = tanhf_(mh.y + r1 * (ah.y + bh.y));
            float hn1 = z1 * hp1 + (1.f - z1) * c1;

            float2 hv = make_float2(hn0, hn1);
            __stcg((float2*)(g_hseq + ((b0 + b) * T_STEPS + t) * UNITS + u0 + u), hv);
            // keep own slice locally for next step
            sh[b * 260 + u0 + u]     = hn0;
            sh[b * 260 + u0 + u + 1] = hn1;
        }

        __syncthreads();
        if (tid == 0) st_release_gpu(&flags[ut], base + (unsigned)t + 1u);
    }
}

// ---------------------------------------------------------------------------
__global__ void copy_out_kernel(float* __restrict__ out) {
    int i = blockIdx.x * 256 + threadIdx.x;
    int b = i >> 8;
    int u = i & 255;
    out[i] = g_hseq[(b * T_STEPS + (T_STEPS - 1)) * UNITS + u];
}

// ---------------------------------------------------------------------------
extern "C" void kernel_launch(void* const* d_in, const int* in_sizes, int n_in,
                              void* d_out, int out_size) {
    (void)in_sizes; (void)n_in; (void)out_size;
    const float* x     = (const float*)d_in[0];
    const float* k0    = (const float*)d_in[1];
    const float* rk0   = (const float*)d_in[2];
    const float* b0    = (const float*)d_in[3];
    const float* kern  = (const float*)d_in[4];
    const float* rkern = (const float*)d_in[5];
    const float* bias  = (const float*)d_in[6];
    float* out = (float*)d_out;

    cudaFuncSetAttribute(scan_kernel,
        cudaFuncAttributeMaxDynamicSharedMemorySize, SCAN_SMEM);

    init_flags_kernel<<<1, 512>>>();

    dim3 ggrid(G3 / 128, MROWS / 128);
    dim3 sgrid(8, 16);

    gemm_kernel<<<ggrid, 256>>>(x, k0, b0, 1);
    scan_kernel<<<sgrid, 256, SCAN_SMEM>>>(rk0, b0 + G3, 0);

    for (int l = 0; l < 3; l++) {
        gemm_kernel<<<ggrid, 256>>>(nullptr, kern + l * 256 * G3,
                                    bias + l * 2 * G3, 0);
        scan_kernel<<<sgrid, 256, SCAN_SMEM>>>(rkern + l * 256 * G3,
                                    bias + l * 2 * G3 + G3,
                                    l + 1);
    }

    copy_out_kernel<<<BATCH, 256>>>(out);
}

// round 4
// speedup vs baseline: 1.2049x; 1.0838x over previous
#include <cuda_runtime.h>
#include <cstdint>
#include <cstddef>

// ---------------------------------------------------------------------------
// GRU stack: 4 layers (256 -> 256), B=128, T=384, reset_after=True (Keras).
// Phase A (per layer): xp = X @ W + b_in   (fp32 GEMM, f32x2 FMA, dbl-buffered)
// Phase B (per layer): persistent scan, 8-CTA clusters per batch tile,
//                      weights in SMEM, h exchanged via DSMEM st.async,
//                      f32x2 packed FMA inner loop.
// ---------------------------------------------------------------------------

#define BATCH   128
#define T_STEPS 384
#define UNITS   256
#define G3      768
#define MROWS   (BATCH * T_STEPS)   // 49152

__device__ float g_xp[MROWS * G3];      // [B*T, 768] input projections
__device__ float g_hseq[MROWS * UNITS]; // [B*T, 256] hidden sequence

// ---------------------------------------------------------------------------
// f32x2 packed math helpers
// ---------------------------------------------------------------------------
typedef unsigned long long ull;

__device__ __forceinline__ ull p2(float x, float y) {
    ull d; asm("mov.b64 %0, {%1, %2};" : "=l"(d) : "f"(x), "f"(y)); return d;
}
__device__ __forceinline__ ull p1(float x) {
    ull d; asm("mov.b64 %0, {%1, %1};" : "=l"(d) : "f"(x)); return d;
}
__device__ __forceinline__ void fma2(ull& acc, ull a, ull b) {
    asm("fma.rn.f32x2 %0, %1, %2, %0;" : "+l"(acc) : "l"(a), "l"(b));
}
__device__ __forceinline__ void add2(ull& acc, ull a) {
    asm("add.rn.f32x2 %0, %1, %0;" : "+l"(acc) : "l"(a));
}
__device__ __forceinline__ float2 unp2(ull d) {
    float2 v; asm("mov.b64 {%0, %1}, %2;" : "=f"(v.x), "=f"(v.y) : "l"(d)); return v;
}

// ---------------------------------------------------------------------------
// cluster / mbarrier helpers
// ---------------------------------------------------------------------------
__device__ __forceinline__ uint32_t smem_u32(const void* p) {
    uint32_t a;
    asm("{ .reg .u64 t; cvta.to.shared.u64 t, %1; cvt.u32.u64 %0, t; }"
        : "=r"(a) : "l"(p));
    return a;
}
__device__ __forceinline__ uint32_t mapa_u32(uint32_t a, uint32_t rank) {
    uint32_t r;
    asm("mapa.shared::cluster.u32 %0, %1, %2;" : "=r"(r) : "r"(a), "r"(rank));
    return r;
}
__device__ __forceinline__ void mbar_init(uint32_t a, uint32_t cnt) {
    asm volatile("mbarrier.init.shared.b64 [%0], %1;" :: "r"(a), "r"(cnt) : "memory");
}
__device__ __forceinline__ void mbar_expect(uint32_t a, uint32_t bytes) {
    asm volatile("mbarrier.arrive.expect_tx.shared.b64 _, [%0], %1;"
                 :: "r"(a), "r"(bytes) : "memory");
}
__device__ __forceinline__ void mbar_arrive_remote(uint32_t a) {
    asm volatile("mbarrier.arrive.shared::cluster.b64 _, [%0];" :: "r"(a) : "memory");
}
// bounded wait: if the protocol ever wedges we return (wrong answer, not a
// container timeout). 1M polls ~ 150M cycles.
__device__ __forceinline__ void mbar_wait_cluster(uint32_t a, int parity) {
    unsigned ok = 0;
    for (int i = 0; i < 1000000; i++) {
        asm volatile(
            "{\n\t.reg .pred P;\n\t"
            "mbarrier.try_wait.parity.acquire.cluster.shared::cta.b64 P, [%1], %2, 0x2000;\n\t"
            "selp.u32 %0, 1, 0, P;\n\t}"
            : "=r"(ok) : "r"(a), "r"((unsigned)parity) : "memory");
        if (ok) break;
    }
}
__device__ __forceinline__ void st_async_b64(uint32_t raddr, ull v, uint32_t rmbar) {
    asm volatile("st.async.shared::cluster.mbarrier::complete_tx::bytes.b64 [%0], %1, [%2];"
                 :: "r"(raddr), "l"(v), "r"(rmbar) : "memory");
}
#define CLUSTER_SYNC_() do {                                          \
    asm volatile("barrier.cluster.arrive.aligned;" ::: "memory");     \
    asm volatile("barrier.cluster.wait.aligned;" ::: "memory");       \
} while (0)

__device__ __forceinline__ float sigm_(float x) {
    return 1.f / (1.f + __expf(-x));
}
__device__ __forceinline__ float tanh_(float x) {
    float s = 1.f / (1.f + __expf(-2.f * x));
    return 2.f * s - 1.f;
}

// ---------------------------------------------------------------------------
// SGEMM: C[M=49152, N=768] = A[M,256] @ W[256,768] + bias_in[768]
// 128x128x8 tiles, 256 threads, 8x8 register tile (as 8x4 f32x2), dbl buffer.
// ---------------------------------------------------------------------------
__global__ __launch_bounds__(256, 2) void gemm_kernel(
    const float* __restrict__ X,
    const float* __restrict__ W,
    const float* __restrict__ bin,
    int use_x)
{
    const int K = 256, N = G3;
    const float* A = use_x ? X : g_hseq;

    __shared__ float As[2][8][128];
    __shared__ float Bs[2][8][128];

    int tid = threadIdx.x;
    int tx = tid & 15;
    int ty = tid >> 4;
    int bm = blockIdx.y * 128;
    int bn = blockIdx.x * 128;

    ull acc[8][4];
#pragma unroll
    for (int i = 0; i < 8; i++)
#pragma unroll
        for (int j = 0; j < 4; j++) acc[i][j] = 0ull;

    int arow = tid >> 1;
    int acol = (tid & 1) * 4;
    int brow = tid >> 5;
    int bcol = (tid & 31) * 4;

    const float* Ap = A + (size_t)(bm + arow) * K + acol;
    const float* Wp = W + (size_t)brow * N + bn + bcol;

    {
        float4 a4 = *(const float4*)(Ap);
        float4 b4 = *(const float4*)(Wp);
        As[0][acol + 0][arow] = a4.x;
        As[0][acol + 1][arow] = a4.y;
        As[0][acol + 2][arow] = a4.z;
        As[0][acol + 3][arow] = a4.w;
        *(float4*)&Bs[0][brow][bcol] = b4;
    }
    __syncthreads();

    int buf = 0;
    for (int k0 = 8; k0 <= K; k0 += 8) {
        float4 a4n, b4n;
        if (k0 < K) {
            a4n = *(const float4*)(Ap + k0);
            b4n = *(const float4*)(Wp + (size_t)k0 * N);
        }
#pragma unroll
        for (int kk = 0; kk < 8; kk++) {
            float4 aA = *(const float4*)&As[buf][kk][ty * 4];
            float4 aB = *(const float4*)&As[buf][kk][64 + ty * 4];
            float4 bA = *(const float4*)&Bs[buf][kk][tx * 4];
            float4 bB = *(const float4*)&Bs[buf][kk][64 + tx * 4];
            ull rap[8];
            rap[0] = p1(aA.x); rap[1] = p1(aA.y); rap[2] = p1(aA.z); rap[3] = p1(aA.w);
            rap[4] = p1(aB.x); rap[5] = p1(aB.y); rap[6] = p1(aB.z); rap[7] = p1(aB.w);
            ull rbp[4];
            rbp[0] = p2(bA.x, bA.y); rbp[1] = p2(bA.z, bA.w);
            rbp[2] = p2(bB.x, bB.y); rbp[3] = p2(bB.z, bB.w);
#pragma unroll
            for (int i = 0; i < 8; i++)
#pragma unroll
                for (int j = 0; j < 4; j++)
                    fma2(acc[i][j], rap[i], rbp[j]);
        }
        if (k0 < K) {
            int nb = buf ^ 1;
            As[nb][acol + 0][arow] = a4n.x;
            As[nb][acol + 1][arow] = a4n.y;
            As[nb][acol + 2][arow] = a4n.z;
            As[nb][acol + 3][arow] = a4n.w;
            *(float4*)&Bs[nb][brow][bcol] = b4n;
            __syncthreads();
            buf = nb;
        }
    }

#pragma unroll
    for (int i = 0; i < 8; i++) {
        int row = (i < 4) ? (ty * 4 + i) : (64 + ty * 4 + (i - 4));
#pragma unroll
        for (int jh = 0; jh < 2; jh++) {
            int col = jh * 64 + tx * 4;
            float2 pa = unp2(acc[i][jh * 2 + 0]);
            float2 pb = unp2(acc[i][jh * 2 + 1]);
            float4 v;
            v.x = pa.x + bin[bn + col + 0];
            v.y = pa.y + bin[bn + col + 1];
            v.z = pb.x + bin[bn + col + 2];
            v.w = pb.y + bin[bn + col + 3];
            *(float4*)&g_xp[(size_t)(bm + row) * N + bn + col] = v;
        }
    }
}

// ---------------------------------------------------------------------------
// Recurrent scan. Grid (8,16); cluster (8,1,1) = the 8 unit-tile CTAs of one
// batch tile. Block: 8 batch rows x 32 units; 96KB weight slice in SMEM.
// h exchanged via DSMEM st.async into double-buffered sh2 with full/empty
// mbarriers. Inner loop: f32x2 FMA, 8-way k-split reduced via SMEM.
// ---------------------------------------------------------------------------
#define OFF_MBAR 0       // full[0]@0, full[1]@8, empty[0]@16, empty[1]@24
#define OFF_W    128     // 6144 float4 = 98304 B  (w4[kp][g][up])
#define OFF_H    98432   // sh2[2][128 kp][8 rows] float2 = 16384 B
#define OFF_RED  114816  // red[8 ks][32 lane][13] u64 = 26624 B
#define SCAN_SMEM (OFF_RED + 26624)

__global__ __launch_bounds__(256, 1) __cluster_dims__(8, 1, 1)
void scan_kernel(const float* __restrict__ RK,    // [256, 768]
                 const float* __restrict__ brec)  // [768]
{
    extern __shared__ char smem[];
    const int tid = threadIdx.x;
    const int ut = blockIdx.x;          // cluster rank
    const int bt = blockIdx.y;
    const int u0 = ut * 32;
    const int b0 = bt * 8;

    const uint32_t sbase = smem_u32(smem);
    float4* sW = (float4*)(smem + OFF_W);
    ull* red = (ull*)(smem + OFF_RED);

    // weight fill: w4[kp][g][up] = (W[2kp][u],W[2kp][u+1],W[2kp+1][u],W[2kp+1][u+1])
    for (int i = tid; i < 6144; i += 256) {
        int kp = i / 48;
        int rem = i - kp * 48;
        int g = rem >> 4;
        int up = rem & 15;
        const float* s0 = RK + (size_t)(2 * kp) * G3 + g * 256 + u0 + 2 * up;
        float2 a = *(const float2*)s0;
        float2 b = *(const float2*)(s0 + G3);
        sW[i] = make_float4(a.x, a.y, b.x, b.y);
    }
    // zero buffer 0 of sh2 (h(-1) = 0)
    {
        float4* z = (float4*)(smem + OFF_H);
        for (int i = tid; i < 8192 / 16; i += 256) z[i] = make_float4(0, 0, 0, 0);
    }
    if (tid == 0) {
        mbar_init(sbase + 0, 1);    // full[0]
        mbar_init(sbase + 8, 1);    // full[1]
        mbar_init(sbase + 16, 8);   // empty[0]: 8 consumer CTAs
        mbar_init(sbase + 24, 8);   // empty[1]
        asm volatile("fence.mbarrier_init.release.cluster;" ::: "memory");
        mbar_expect(sbase + 8, 8192);   // pre-arm full[1] for the h(0) fill
    }
    __syncthreads();
    CLUSTER_SYNC_();

    const int ks = tid >> 5;        // 0..7 k-split
    const int lane = tid & 31;
    const int bg = lane >> 4;       // 0..1 row half
    const int up = lane & 15;       // 0..15 unit pair
    const int kp0 = ks * 16;

    const int fb = tid >> 4;        // finalist: 0..7 local row (tid < 128)
    const int fu = tid & 15;        // finalist: unit pair
    const int bgF = fb >> 2;
    const int rF = fb & 3;

    float2 bzv = make_float2(0, 0), brv = make_float2(0, 0), bhv = make_float2(0, 0);
    if (tid < 128) {
        bzv = *(const float2*)(brec + 0   + u0 + 2 * fu);
        brv = *(const float2*)(brec + 256 + u0 + 2 * fu);
        bhv = *(const float2*)(brec + 512 + u0 + 2 * fu);
    }

    int fullp[2] = {0, 0};
    // buffer 1's first producer-wait (t=0) precedes any release -> parity 1
    // buffer 0's first producer-wait (t=1) pairs with the release at t=0 -> parity 0
    int emptyp[2] = {0, 1};

    for (int t = 0; t < T_STEPS; t++) {
        const int v = t & 1;
        const int w = v ^ 1;

        // prefetch xp(t) (finalists) before any waiting
        float2 mzv, mrv, mhv;
        if (tid < 128) {
            const float* xr = g_xp + ((size_t)(b0 + fb) * T_STEPS + t) * G3;
            mzv = *(const float2*)(xr + 0   + u0 + 2 * fu);
            mrv = *(const float2*)(xr + 256 + u0 + 2 * fu);
            mhv = *(const float2*)(xr + 512 + u0 + 2 * fu);
        }

        if (t > 0) { mbar_wait_cluster(sbase + v * 8, fullp[v]); fullp[v] ^= 1; }

        // partial GEMM over this thread's 16 unit-pairs of k
        ull acc[4][3];
#pragma unroll
        for (int r = 0; r < 4; r++)
#pragma unroll
            for (int g = 0; g < 3; g++) acc[r][g] = 0ull;

        const char* hbuf = smem + OFF_H + v * 8192;
#pragma unroll 4
        for (int kp = kp0; kp < kp0 + 16; kp++) {
            float4 hA = *(const float4*)(hbuf + kp * 64 + bg * 32);
            float4 hB = *(const float4*)(hbuf + kp * 64 + bg * 32 + 16);
            ull h0[4], h1[4];
            h0[0] = p1(hA.x); h1[0] = p1(hA.y);
            h0[1] = p1(hA.z); h1[1] = p1(hA.w);
            h0[2] = p1(hB.x); h1[2] = p1(hB.y);
            h0[3] = p1(hB.z); h1[3] = p1(hB.w);
#pragma unroll
            for (int g = 0; g < 3; g++) {
                float4 wv = sW[kp * 48 + g * 16 + up];
                ull w01 = p2(wv.x, wv.y);
                ull w23 = p2(wv.z, wv.w);
#pragma unroll
                for (int r = 0; r < 4; r++) {
                    fma2(acc[r][g], h0[r], w01);
                    fma2(acc[r][g], h1[r], w23);
                }
            }
        }

        // own h_prev (must read buffer v before releasing it)
        float2 hp = make_float2(0, 0);
        if (tid < 128)
            hp = *(const float2*)(hbuf + ((ut * 16 + fu) * 8 + fb) * 8);

        // store partials
        {
            ull* my = red + (size_t)(ks * 32 + lane) * 13;
#pragma unroll
            for (int g = 0; g < 3; g++)
#pragma unroll
                for (int r = 0; r < 4; r++)
                    my[g * 4 + r] = acc[r][g];
        }
        __syncthreads();

        // buffer v fully consumed: arm its next fill, release it cluster-wide
        if (tid == 0 && t <= T_STEPS - 3) {
            mbar_expect(sbase + v * 8, 8192);      // h(t+1) -> buffer v
            uint32_t emb = sbase + 16 + v * 8;
#pragma unroll
            for (int c = 0; c < 8; c++)
                mbar_arrive_remote(mapa_u32(emb, c));
        }

        if (tid < 128) {
            // reduce 8 k-partials
            ull s[3];
#pragma unroll
            for (int g = 0; g < 3; g++) {
                ull a = red[(size_t)(bgF * 16 + fu) * 13 + g * 4 + rF];
#pragma unroll
                for (int k2 = 1; k2 < 8; k2++)
                    add2(a, red[(size_t)(k2 * 32 + bgF * 16 + fu) * 13 + g * 4 + rF]);
                s[g] = a;
            }
            float2 az = unp2(s[0]);
            float2 ar = unp2(s[1]);
            float2 ah = unp2(s[2]);

            float z0 = sigm_(mzv.x + az.x + bzv.x);
            float r0 = sigm_(mrv.x + ar.x + brv.x);
            float c0 = tanh_(mhv.x + r0 * (ah.x + bhv.x));
            float hn0 = z0 * hp.x + (1.f - z0) * c0;

            float z1 = sigm_(mzv.y + az.y + bzv.y);
            float r1 = sigm_(mrv.y + ar.y + brv.y);
            float c1 = tanh_(mhv.y + r1 * (ah.y + bhv.y));
            float hn1 = z1 * hp.y + (1.f - z1) * c1;

            // hidden sequence to global (next layer's GEMM input / final output)
            *(float2*)(g_hseq + ((size_t)(b0 + fb) * T_STEPS + t) * UNITS + u0 + 2 * fu)
                = make_float2(hn0, hn1);

            // broadcast h(t) into all 8 cluster CTAs' buffer w
            if (t <= T_STEPS - 2) {
                mbar_wait_cluster(sbase + 16 + w * 8, emptyp[w]); emptyp[w] ^= 1;
                ull hn = p2(hn0, hn1);
                uint32_t dl = sbase + OFF_H + w * 8192 + ((ut * 16 + fu) * 8 + fb) * 8;
                uint32_t ml = sbase + w * 8;   // target's full[w]
#pragma unroll
                for (int c = 0; c < 8; c++)
                    st_async_b64(mapa_u32(dl, c), hn, mapa_u32(ml, c));
            }
        }
    }
    CLUSTER_SYNC_();
}

// ---------------------------------------------------------------------------
__global__ void copy_out_kernel(float* __restrict__ out) {
    int i = blockIdx.x * 256 + threadIdx.x;
    int b = i >> 8;
    int u = i & 255;
    out[i] = g_hseq[((size_t)b * T_STEPS + (T_STEPS - 1)) * UNITS + u];
}

// ---------------------------------------------------------------------------
extern "C" void kernel_launch(void* const* d_in, const int* in_sizes, int n_in,
                              void* d_out, int out_size) {
    (void)in_sizes; (void)n_in; (void)out_size;
    const float* x     = (const float*)d_in[0];
    const float* k0    = (const float*)d_in[1];
    const float* rk0   = (const float*)d_in[2];
    const float* b0    = (const float*)d_in[3];
    const float* kern  = (const float*)d_in[4];
    const float* rkern = (const float*)d_in[5];
    const float* bias  = (const float*)d_in[6];
    float* out = (float*)d_out;

    cudaFuncSetAttribute(scan_kernel,
        cudaFuncAttributeMaxDynamicSharedMemorySize, SCAN_SMEM);

    dim3 ggrid(G3 / 128, MROWS / 128);
    dim3 sgrid(8, 16);

    gemm_kernel<<<ggrid, 256>>>(x, k0, b0, 1);
    scan_kernel<<<sgrid, 256, SCAN_SMEM>>>(rk0, b0 + G3);

    for (int l = 0; l < 3; l++) {
        gemm_kernel<<<ggrid, 256>>>(nullptr, kern + (size_t)l * 256 * G3,
                                    bias + (size_t)l * 2 * G3, 0);
        scan_kernel<<<sgrid, 256, SCAN_SMEM>>>(rkern + (size_t)l * 256 * G3,
                                    bias + (size_t)l * 2 * G3 + G3);
    }

    copy_out_kernel<<<BATCH, 256>>>(out);
}